// round 12
// baseline (speedup 1.0000x reference)
#include <cuda_runtime.h>
#include <cuda_fp16.h>
#include <cstdint>
#include <cstddef>

// ============================================================================
// MultiHeadAttention on GB300 — FP16 mma.sync everywhere.
//   conv : x, W -> fp16 (single fused launch)
//   GEMM : persistent CTAs (296), CTA tile 128x128, warp 64x32, 2 CTA/SM,
//          4-stage cp.async pipeline + register fragment double-buffering
//   attn : per-token 16x16 head attention on tensor cores
// ============================================================================

#define NSTG 4
#define STAGE_B 16384          // A 8KB + B 8KB
#define CTA_M 128
#define CTA_N 128
#define SMEM_TOTAL (NSTG * STAGE_B)   // 65536
#define PERSIST_CTAS 296

__device__ __half g_Yh[50331648];   // 16384 x 3072
__device__ __half g_Oh[16777216];   // 16384 x 1024
__device__ __half g_Xh[16777216];   // x in fp16
__device__ __half g_Wh[4194304];    // Wq|Wk|Wv|Wfc in fp16

// ---------------------------------------------------------------- helpers
__device__ __forceinline__ uint32_t smem_u32(const void* p) {
    uint32_t a;
    asm("{ .reg .u64 t; cvta.to.shared.u64 t, %1; cvt.u32.u64 %0, t; }"
        : "=r"(a) : "l"(p));
    return a;
}
__device__ __forceinline__ void cp16(uint32_t saddr, const void* gptr) {
    asm volatile("cp.async.cg.shared.global [%0], [%1], 16;\n" :: "r"(saddr), "l"(gptr));
}
__device__ __forceinline__ void cp_commit() { asm volatile("cp.async.commit_group;\n"); }
template <int N>
__device__ __forceinline__ void cp_wait() {
    asm volatile("cp.async.wait_group %0;\n" :: "n"(N));
}
__device__ __forceinline__ void ldsm4(uint32_t& r0, uint32_t& r1, uint32_t& r2,
                                      uint32_t& r3, uint32_t addr) {
    asm volatile("ldmatrix.sync.aligned.m8n8.x4.shared.b16 {%0,%1,%2,%3}, [%4];"
                 : "=r"(r0), "=r"(r1), "=r"(r2), "=r"(r3) : "r"(addr));
}
__device__ __forceinline__ void ldsm4t(uint32_t& r0, uint32_t& r1, uint32_t& r2,
                                       uint32_t& r3, uint32_t addr) {
    asm volatile("ldmatrix.sync.aligned.m8n8.x4.trans.shared.b16 {%0,%1,%2,%3}, [%4];"
                 : "=r"(r0), "=r"(r1), "=r"(r2), "=r"(r3) : "r"(addr));
}
__device__ __forceinline__ void mma_f16(float c[4], const uint32_t a[4], const uint32_t b[2]) {
    asm volatile(
        "mma.sync.aligned.m16n8k16.row.col.f32.f16.f16.f32 "
        "{%0,%1,%2,%3}, {%4,%5,%6,%7}, {%8,%9}, {%0,%1,%2,%3};\n"
        : "+f"(c[0]), "+f"(c[1]), "+f"(c[2]), "+f"(c[3])
        : "r"(a[0]), "r"(a[1]), "r"(a[2]), "r"(a[3]), "r"(b[0]), "r"(b[1]));
}

// ============================================================================
// Persistent FP16 NT GEMM: C = A[M,K] @ B[N,K]^T, tiles 128x128.
// Each CTA loops over tile ids t = bid, bid+grid, ... (ntile = t % NTN).
// ============================================================================
template <bool OUT_HALF>
__global__ void __launch_bounds__(256, 2)
gemm_f16_nt(const __half* __restrict__ A, const __half* __restrict__ B,
            void* __restrict__ Cout, int ldc, int K, int NTN, int NTOT)
{
    extern __shared__ __align__(128) char smem[];
    const uint32_t sb = smem_u32(smem);

    const int tid  = threadIdx.x;
    const int lane = tid & 31;
    const int wid  = tid >> 5;
    const int warp_m = wid & 1;     // 64 rows
    const int warp_n = wid >> 1;    // 32 cols

    // per-thread loader slot geometry (tile-independent parts)
    int l_op[4], l_rr[4], l_g[4];
    uint32_t soff[4];
#pragma unroll
    for (int i = 0; i < 4; i++) {
        const int id = tid + i * 256;       // 0..1023
        l_op[i] = id >> 9;                  // 0=A 1=B
        l_rr[i] = (id >> 2) & 127;
        l_g[i]  = id & 3;
        soff[i] = (uint32_t)(l_op[i] * 8192 + l_rr[i] * 64 +
                             ((l_g[i] ^ ((l_rr[i] >> 1) & 3)) << 4));
    }

    // ldmatrix fragment base addresses (stage 0, ks=0) — tile-independent
    const int ch = lane >> 4;
    uint32_t a_addr[4], b_addr[2];
#pragma unroll
    for (int mt = 0; mt < 4; mt++) {
        const int r = warp_m * 64 + mt * 16 + (lane & 15);
        a_addr[mt] = sb + r * 64 + ((ch ^ ((r >> 1) & 3)) << 4);
    }
#pragma unroll
    for (int p = 0; p < 2; p++) {
        const int r = warp_n * 32 + p * 16 + (lane & 15);
        b_addr[p] = sb + 8192 + r * 64 + ((ch ^ ((r >> 1) & 3)) << 4);
    }

    const int NKT = K >> 5;   // multiple of 4

    uint32_t aS[2][4][4], bS[2][4][2];

    for (int t = blockIdx.x; t < NTOT; t += gridDim.x) {
        const int mtile = t / NTN;
        const int ntile = t - mtile * NTN;
        const __half* Ab = A + (size_t)(mtile * CTA_M) * K;
        const __half* Bb = B + (size_t)(ntile * CTA_N) * K;

        const __half* gsrc[4];
#pragma unroll
        for (int i = 0; i < 4; i++)
            gsrc[i] = (l_op[i] ? Bb : Ab) + (size_t)l_rr[i] * K + l_g[i] * 8;

        float acc[4][4][4];
#pragma unroll
        for (int mt = 0; mt < 4; mt++)
#pragma unroll
            for (int nt = 0; nt < 4; nt++)
#pragma unroll
                for (int i = 0; i < 4; i++) acc[mt][nt][i] = 0.f;

        auto ld_slot = [&](int s, uint32_t so, uint32_t kx) {
#pragma unroll
            for (int mt = 0; mt < 4; mt++)
                ldsm4(aS[s][mt][0], aS[s][mt][1], aS[s][mt][2], aS[s][mt][3],
                      (a_addr[mt] + so) ^ kx);
#pragma unroll
            for (int p = 0; p < 2; p++) {
                uint32_t t0, t1, t2, t3;
                ldsm4(t0, t1, t2, t3, (b_addr[p] + so) ^ kx);
                bS[s][2 * p][0] = t0; bS[s][2 * p][1] = t2;
                bS[s][2 * p + 1][0] = t1; bS[s][2 * p + 1][1] = t3;
            }
        };
        auto do_mma = [&](int s) {
#pragma unroll
            for (int mt = 0; mt < 4; mt++)
#pragma unroll
                for (int nt = 0; nt < 4; nt++)
                    mma_f16(acc[mt][nt], aS[s][mt], bS[s][nt]);
        };

        // drain stale groups, and ensure all warps finished reading old stages
        cp_wait<0>();
        __syncthreads();

        // prefill stages 0..2 with k-tiles 0..2
#pragma unroll
        for (int s = 0; s < NSTG - 1; s++) {
#pragma unroll
            for (int i = 0; i < 4; i++)
                cp16(sb + s * STAGE_B + soff[i], gsrc[i] + s * 32);
            cp_commit();
        }

        cp_wait<2>();
        __syncthreads();
        ld_slot(0, 0, 0);          // fragments for (tile 0, ks 0)

        for (int kt0 = 0; kt0 < NKT; kt0 += 4) {
#pragma unroll
            for (int u = 0; u < 4; u++) {
                cp_wait<1>();            // tiles kt, kt+1 resident (per thread)
                __syncthreads();         // visibility + stage (u+3)&3 free

                const int nk = kt0 + u + 3;
                const uint32_t sw = (uint32_t)((u + 3) & 3) * STAGE_B;
                if (nk < NKT) {
#pragma unroll
                    for (int i = 0; i < 4; i++)
                        cp16(sb + sw + soff[i], gsrc[i] + nk * 32);
                }
                cp_commit();

                const uint32_t so  = (uint32_t)u * STAGE_B;
                const uint32_t son = (uint32_t)((u + 1) & 3) * STAGE_B;

                ld_slot(1, so, 32);      // (kt, ks1)
                do_mma(0);               // (kt, ks0)
                ld_slot(0, son, 0);      // (kt+1, ks0); stale on last iter, unused
                do_mma(1);               // (kt, ks1)
            }
        }

        // -------- epilogue (registers only; no smem reads)
        const int r_in = lane >> 2;
        const int c_in = 2 * (lane & 3);
        if (OUT_HALF) {
            __half* Cb = (__half*)Cout + (size_t)(mtile * CTA_M) * ldc
                       + (size_t)ntile * CTA_N;
#pragma unroll
            for (int mt = 0; mt < 4; mt++)
#pragma unroll
                for (int nt = 0; nt < 4; nt++) {
                    const int r0 = warp_m * 64 + mt * 16 + r_in;
                    const int c0 = warp_n * 32 + nt * 8 + c_in;
                    *(__half2*)(Cb + (size_t)r0 * ldc + c0) =
                        __floats2half2_rn(acc[mt][nt][0], acc[mt][nt][1]);
                    *(__half2*)(Cb + (size_t)(r0 + 8) * ldc + c0) =
                        __floats2half2_rn(acc[mt][nt][2], acc[mt][nt][3]);
                }
        } else {
            float* Cb = (float*)Cout + (size_t)(mtile * CTA_M) * ldc
                      + (size_t)ntile * CTA_N;
#pragma unroll
            for (int mt = 0; mt < 4; mt++)
#pragma unroll
                for (int nt = 0; nt < 4; nt++) {
                    const int r0 = warp_m * 64 + mt * 16 + r_in;
                    const int c0 = warp_n * 32 + nt * 8 + c_in;
                    *(float2*)(Cb + (size_t)r0 * ldc + c0) =
                        make_float2(acc[mt][nt][0], acc[mt][nt][1]);
                    *(float2*)(Cb + (size_t)(r0 + 8) * ldc + c0) =
                        make_float2(acc[mt][nt][2], acc[mt][nt][3]);
                }
        }
    }
}

// ============================================================================
// fused fp32 -> fp16 converter
// ============================================================================
__global__ void __launch_bounds__(256)
f2h_all(const float4* __restrict__ x,
        const float4* __restrict__ w0, const float4* __restrict__ w1,
        const float4* __restrict__ w2, const float4* __restrict__ w3,
        uint2* __restrict__ xdst, uint2* __restrict__ wdst)
{
    const int bx = blockIdx.x;
    const float4* src;
    uint2* dst;
    int i;
    if (bx < 16384) {
        i = bx * 256 + threadIdx.x;
        src = x; dst = xdst;
    } else {
        const int b = bx - 16384;
        const int mm = b >> 10;
        i = (b & 1023) * 256 + threadIdx.x;
        src = (mm == 0) ? w0 : (mm == 1) ? w1 : (mm == 2) ? w2 : w3;
        dst = wdst + (size_t)mm * 262144;
    }
    float4 v = src[i];
    __half2 h0 = __floats2half2_rn(v.x, v.y);
    __half2 h1 = __floats2half2_rn(v.z, v.w);
    uint2 o;
    o.x = *(uint32_t*)&h0;
    o.y = *(uint32_t*)&h1;
    dst[i] = o;
}

// ============================================================================
// Tensor-core per-token head attention (unchanged from R8).
// ============================================================================
#define TPAD 72
#define TOK_H (3 * 16 * TPAD)
#define ATTN_SMEM (8 * TOK_H * 2)

__global__ void __launch_bounds__(256)
attn_tc(const __half* __restrict__ Y, __half* __restrict__ O)
{
    extern __shared__ __align__(16) __half smh[];

    const int lane = threadIdx.x & 31;
    const int w    = threadIdx.x >> 5;
    const int m    = blockIdx.x * 8 + w;

    __half* tok = smh + w * TOK_H;
    const uint32_t tb = smem_u32(tok);

    const uint4* src = (const uint4*)(Y + (size_t)m * 3072);
#pragma unroll
    for (int it = 0; it < 12; it++) {
        const int f   = it * 32 + lane;
        const int sec = f >> 7;
        const int wi  = f & 127;
        const int row = wi >> 3;
        const int c8  = wi & 7;
        *(uint4*)(tok + sec * (16 * TPAD) + row * TPAD + c8 * 8) = src[f];
    }
    __syncwarp();

    const int rr = (lane & 7) + ((lane >> 3) & 1) * 8;
    const int cb = (lane >> 4) * 8;
    const uint32_t loff = (uint32_t)(rr * TPAD + cb) * 2;
    const uint32_t kbase = tb + 16 * TPAD * 2;
    const uint32_t vbase = tb + 32 * TPAD * 2;

    float s0[4] = {0.f, 0.f, 0.f, 0.f};
    float s1[4] = {0.f, 0.f, 0.f, 0.f};
#pragma unroll
    for (int kc = 0; kc < 4; kc++) {
        uint32_t a[4], kb[4];
        ldsm4(a[0], a[1], a[2], a[3], tb + loff + kc * 32);
        ldsm4(kb[0], kb[1], kb[2], kb[3], kbase + loff + kc * 32);
        uint32_t b0[2] = { kb[0], kb[2] };
        uint32_t b1[2] = { kb[1], kb[3] };
        mma_f16(s0, a, b0);
        mma_f16(s1, a, b1);
    }

#pragma unroll
    for (int i = 0; i < 4; i++) { s0[i] *= 0.125f; s1[i] *= 0.125f; }

    float mA = fmaxf(fmaxf(s0[0], s0[1]), fmaxf(s1[0], s1[1]));
    float mB = fmaxf(fmaxf(s0[2], s0[3]), fmaxf(s1[2], s1[3]));
    mA = fmaxf(mA, __shfl_xor_sync(0xffffffff, mA, 1));
    mA = fmaxf(mA, __shfl_xor_sync(0xffffffff, mA, 2));
    mB = fmaxf(mB, __shfl_xor_sync(0xffffffff, mB, 1));
    mB = fmaxf(mB, __shfl_xor_sync(0xffffffff, mB, 2));

    float eA0 = __expf(s0[0] - mA), eA1 = __expf(s0[1] - mA);
    float eA2 = __expf(s1[0] - mA), eA3 = __expf(s1[1] - mA);
    float eB0 = __expf(s0[2] - mB), eB1 = __expf(s0[3] - mB);
    float eB2 = __expf(s1[2] - mB), eB3 = __expf(s1[3] - mB);

    float sA = eA0 + eA1 + eA2 + eA3;
    float sB = eB0 + eB1 + eB2 + eB3;
    sA += __shfl_xor_sync(0xffffffff, sA, 1);
    sA += __shfl_xor_sync(0xffffffff, sA, 2);
    sB += __shfl_xor_sync(0xffffffff, sB, 1);
    sB += __shfl_xor_sync(0xffffffff, sB, 2);
    const float iA = 1.f / sA, iB = 1.f / sB;

    uint32_t pa[4];
    __half2 h;
    h = __floats2half2_rn(eA0 * iA, eA1 * iA); pa[0] = *(uint32_t*)&h;
    h = __floats2half2_rn(eB0 * iB, eB1 * iB); pa[1] = *(uint32_t*)&h;
    h = __floats2half2_rn(eA2 * iA, eA3 * iA); pa[2] = *(uint32_t*)&h;
    h = __floats2half2_rn(eB2 * iB, eB3 * iB); pa[3] = *(uint32_t*)&h;

    float oc[8][4];
#pragma unroll
    for (int i = 0; i < 8; i++)
#pragma unroll
        for (int j = 0; j < 4; j++) oc[i][j] = 0.f;

#pragma unroll
    for (int dc = 0; dc < 4; dc++) {
        uint32_t vb[4];
        ldsm4t(vb[0], vb[1], vb[2], vb[3], vbase + loff + dc * 32);
        uint32_t bt0[2] = { vb[0], vb[1] };
        uint32_t bt1[2] = { vb[2], vb[3] };
        mma_f16(oc[2 * dc], pa, bt0);
        mma_f16(oc[2 * dc + 1], pa, bt1);
    }

    __half* dst = O + (size_t)m * 1024;
    const int r = lane >> 2;
    const int q2 = 2 * (lane & 3);
#pragma unroll
    for (int i = 0; i < 8; i++) {
        const int col = (i >> 1) * 16 + (i & 1) * 8 + q2;
        *(__half2*)(dst + r * 64 + col) =
            __floats2half2_rn(oc[i][0], oc[i][1]);
        *(__half2*)(dst + (r + 8) * 64 + col) =
            __floats2half2_rn(oc[i][2], oc[i][3]);
    }
}

// ============================================================================
extern "C" void kernel_launch(void* const* d_in, const int* in_sizes, int n_in,
                              void* d_out, int out_size)
{
    (void)in_sizes; (void)n_in; (void)out_size;
    const float* x   = (const float*)d_in[0];
    const float* Wq  = (const float*)d_in[1];
    const float* Wk  = (const float*)d_in[2];
    const float* Wv  = (const float*)d_in[3];
    const float* Wfc = (const float*)d_in[4];
    float* out = (float*)d_out;

    __half *Yh, *Oh, *Xh, *Wh;
    cudaGetSymbolAddress((void**)&Yh, g_Yh);
    cudaGetSymbolAddress((void**)&Oh, g_Oh);
    cudaGetSymbolAddress((void**)&Xh, g_Xh);
    cudaGetSymbolAddress((void**)&Wh, g_Wh);

    cudaFuncSetAttribute(gemm_f16_nt<true>,
                         cudaFuncAttributeMaxDynamicSharedMemorySize, SMEM_TOTAL);
    cudaFuncSetAttribute(gemm_f16_nt<false>,
                         cudaFuncAttributeMaxDynamicSharedMemorySize, SMEM_TOTAL);
    cudaFuncSetAttribute(attn_tc,
                         cudaFuncAttributeMaxDynamicSharedMemorySize, ATTN_SMEM);

    // fused fp16 conversion
    f2h_all<<<20480, 256>>>((const float4*)x,
                            (const float4*)Wq, (const float4*)Wk,
                            (const float4*)Wv, (const float4*)Wfc,
                            (uint2*)Xh, (uint2*)Wh);

    // GEMM1: Yh = Xh @ [Wq;Wk;Wv]^T  (24 x 128 tiles, persistent)
    gemm_f16_nt<true><<<PERSIST_CTAS, 256, SMEM_TOTAL>>>(
        Xh, Wh, Yh, 3072, 1024, 24, 24 * 128);
    // tensor-core attention (8 tokens per block)
    attn_tc<<<2048, 256, ATTN_SMEM>>>(Yh, Oh);
    // GEMM2: out = Oh @ Wfc^T        (8 x 128 tiles, persistent)
    gemm_f16_nt<false><<<PERSIST_CTAS, 256, SMEM_TOTAL>>>(
        Oh, Wh + 3145728, out, 1024, 1024, 8, 8 * 128);
}

// round 13
// speedup vs baseline: 1.0048x; 1.0048x over previous
#include <cuda_runtime.h>
#include <cuda_fp16.h>
#include <cstdint>
#include <cstddef>

// ============================================================================
// MultiHeadAttention on GB300 — FP16 mma.sync everywhere.
//   conv : x, W -> fp16 (single fused launch)
//   GEMM1: persistent CTAs (296), tile 128x128, warp 64x32, 2 CTA/SM,
//          4-stage cp.async + register fragment double-buffering
//   attn : per-token 16x16 head attention on tensor cores
//   GEMM2: same inner loop, non-persistent (one tile per CTA)
// ============================================================================

#define NSTG 4
#define STAGE_B 16384          // A 8KB + B 8KB
#define CTA_M 128
#define CTA_N 128
#define SMEM_TOTAL (NSTG * STAGE_B)   // 65536
#define PERSIST_CTAS 296

__device__ __half g_Yh[50331648];   // 16384 x 3072
__device__ __half g_Oh[16777216];   // 16384 x 1024
__device__ __half g_Xh[16777216];   // x in fp16
__device__ __half g_Wh[4194304];    // Wq|Wk|Wv|Wfc in fp16

// ---------------------------------------------------------------- helpers
__device__ __forceinline__ uint32_t smem_u32(const void* p) {
    uint32_t a;
    asm("{ .reg .u64 t; cvta.to.shared.u64 t, %1; cvt.u32.u64 %0, t; }"
        : "=r"(a) : "l"(p));
    return a;
}
__device__ __forceinline__ void cp16(uint32_t saddr, const void* gptr) {
    asm volatile("cp.async.cg.shared.global [%0], [%1], 16;\n" :: "r"(saddr), "l"(gptr));
}
__device__ __forceinline__ void cp_commit() { asm volatile("cp.async.commit_group;\n"); }
template <int N>
__device__ __forceinline__ void cp_wait() {
    asm volatile("cp.async.wait_group %0;\n" :: "n"(N));
}
__device__ __forceinline__ void ldsm4(uint32_t& r0, uint32_t& r1, uint32_t& r2,
                                      uint32_t& r3, uint32_t addr) {
    asm volatile("ldmatrix.sync.aligned.m8n8.x4.shared.b16 {%0,%1,%2,%3}, [%4];"
                 : "=r"(r0), "=r"(r1), "=r"(r2), "=r"(r3) : "r"(addr));
}
__device__ __forceinline__ void ldsm4t(uint32_t& r0, uint32_t& r1, uint32_t& r2,
                                       uint32_t& r3, uint32_t addr) {
    asm volatile("ldmatrix.sync.aligned.m8n8.x4.trans.shared.b16 {%0,%1,%2,%3}, [%4];"
                 : "=r"(r0), "=r"(r1), "=r"(r2), "=r"(r3) : "r"(addr));
}
__device__ __forceinline__ void mma_f16(float c[4], const uint32_t a[4], const uint32_t b[2]) {
    asm volatile(
        "mma.sync.aligned.m16n8k16.row.col.f32.f16.f16.f32 "
        "{%0,%1,%2,%3}, {%4,%5,%6,%7}, {%8,%9}, {%0,%1,%2,%3};\n"
        : "+f"(c[0]), "+f"(c[1]), "+f"(c[2]), "+f"(c[3])
        : "r"(a[0]), "r"(a[1]), "r"(a[2]), "r"(a[3]), "r"(b[0]), "r"(b[1]));
}

// ============================================================================
// FP16 NT GEMM: C = A[M,K] @ B[N,K]^T, tiles 128x128, warp 64x32, 2 CTA/SM.
// PERSIST=true : grid of PERSIST_CTAS loops over tiles t += gridDim.x
// PERSIST=false: one tile per CTA (grid = (NTN, NTM))
// ============================================================================
template <bool OUT_HALF, bool PERSIST>
__global__ void __launch_bounds__(256, 2)
gemm_f16_nt(const __half* __restrict__ A, const __half* __restrict__ B,
            void* __restrict__ Cout, int ldc, int K, int NTN, int NTOT)
{
    extern __shared__ __align__(128) char smem[];
    const uint32_t sb = smem_u32(smem);

    const int tid  = threadIdx.x;
    const int lane = tid & 31;
    const int wid  = tid >> 5;
    const int warp_m = wid & 1;     // 64 rows
    const int warp_n = wid >> 1;    // 32 cols

    // per-thread loader slot geometry (tile-independent)
    int l_op[4], l_rr[4], l_g[4];
    uint32_t soff[4];
#pragma unroll
    for (int i = 0; i < 4; i++) {
        const int id = tid + i * 256;       // 0..1023
        l_op[i] = id >> 9;                  // 0=A 1=B
        l_rr[i] = (id >> 2) & 127;
        l_g[i]  = id & 3;
        soff[i] = (uint32_t)(l_op[i] * 8192 + l_rr[i] * 64 +
                             ((l_g[i] ^ ((l_rr[i] >> 1) & 3)) << 4));
    }

    // ldmatrix fragment base addresses (stage 0, ks=0)
    const int ch = lane >> 4;
    uint32_t a_addr[4], b_addr[2];
#pragma unroll
    for (int mt = 0; mt < 4; mt++) {
        const int r = warp_m * 64 + mt * 16 + (lane & 15);
        a_addr[mt] = sb + r * 64 + ((ch ^ ((r >> 1) & 3)) << 4);
    }
#pragma unroll
    for (int p = 0; p < 2; p++) {
        const int r = warp_n * 32 + p * 16 + (lane & 15);
        b_addr[p] = sb + 8192 + r * 64 + ((ch ^ ((r >> 1) & 3)) << 4);
    }

    const int NKT = K >> 5;   // multiple of 4

    uint32_t aS[2][4][4], bS[2][4][2];

    const int t_begin = PERSIST ? blockIdx.x : (blockIdx.y * NTN + blockIdx.x);
    const int t_step  = PERSIST ? gridDim.x : NTOT;   // non-persist: single pass

    for (int t = t_begin; t < NTOT; t += t_step) {
        const int mtile = t / NTN;
        const int ntile = t - mtile * NTN;
        const __half* Ab = A + (size_t)(mtile * CTA_M) * K;
        const __half* Bb = B + (size_t)(ntile * CTA_N) * K;

        const __half* gsrc[4];
#pragma unroll
        for (int i = 0; i < 4; i++)
            gsrc[i] = (l_op[i] ? Bb : Ab) + (size_t)l_rr[i] * K + l_g[i] * 8;

        float acc[4][4][4];
#pragma unroll
        for (int mt = 0; mt < 4; mt++)
#pragma unroll
            for (int nt = 0; nt < 4; nt++)
#pragma unroll
                for (int i = 0; i < 4; i++) acc[mt][nt][i] = 0.f;

        auto ld_slot = [&](int s, uint32_t so, uint32_t kx) {
#pragma unroll
            for (int mt = 0; mt < 4; mt++)
                ldsm4(aS[s][mt][0], aS[s][mt][1], aS[s][mt][2], aS[s][mt][3],
                      (a_addr[mt] + so) ^ kx);
#pragma unroll
            for (int p = 0; p < 2; p++) {
                uint32_t t0, t1, t2, t3;
                ldsm4(t0, t1, t2, t3, (b_addr[p] + so) ^ kx);
                bS[s][2 * p][0] = t0; bS[s][2 * p][1] = t2;
                bS[s][2 * p + 1][0] = t1; bS[s][2 * p + 1][1] = t3;
            }
        };
        auto do_mma = [&](int s) {
#pragma unroll
            for (int mt = 0; mt < 4; mt++)
#pragma unroll
                for (int nt = 0; nt < 4; nt++)
                    mma_f16(acc[mt][nt], aS[s][mt], bS[s][nt]);
        };

        if (PERSIST) {
            // drain stale groups; ensure all warps done reading old stages
            cp_wait<0>();
            __syncthreads();
        }

        // prefill stages 0..2 with k-tiles 0..2
#pragma unroll
        for (int s = 0; s < NSTG - 1; s++) {
#pragma unroll
            for (int i = 0; i < 4; i++)
                cp16(sb + s * STAGE_B + soff[i], gsrc[i] + s * 32);
            cp_commit();
        }

        cp_wait<2>();
        __syncthreads();
        ld_slot(0, 0, 0);          // fragments for (tile 0, ks 0)

        for (int kt0 = 0; kt0 < NKT; kt0 += 4) {
#pragma unroll
            for (int u = 0; u < 4; u++) {
                cp_wait<1>();            // tiles kt, kt+1 resident
                __syncthreads();         // stage (u+3)&3 free

                const int nk = kt0 + u + 3;
                const uint32_t sw = (uint32_t)((u + 3) & 3) * STAGE_B;
                if (nk < NKT) {
#pragma unroll
                    for (int i = 0; i < 4; i++)
                        cp16(sb + sw + soff[i], gsrc[i] + nk * 32);
                }
                cp_commit();

                const uint32_t so  = (uint32_t)u * STAGE_B;
                const uint32_t son = (uint32_t)((u + 1) & 3) * STAGE_B;

                ld_slot(1, so, 32);      // (kt, ks1)
                do_mma(0);               // (kt, ks0)
                ld_slot(0, son, 0);      // (kt+1, ks0); stale on last iter, unused
                do_mma(1);               // (kt, ks1)
            }
        }

        // -------- epilogue (registers only)
        const int r_in = lane >> 2;
        const int c_in = 2 * (lane & 3);
        if (OUT_HALF) {
            __half* Cb = (__half*)Cout + (size_t)(mtile * CTA_M) * ldc
                       + (size_t)ntile * CTA_N;
#pragma unroll
            for (int mt = 0; mt < 4; mt++)
#pragma unroll
                for (int nt = 0; nt < 4; nt++) {
                    const int r0 = warp_m * 64 + mt * 16 + r_in;
                    const int c0 = warp_n * 32 + nt * 8 + c_in;
                    *(__half2*)(Cb + (size_t)r0 * ldc + c0) =
                        __floats2half2_rn(acc[mt][nt][0], acc[mt][nt][1]);
                    *(__half2*)(Cb + (size_t)(r0 + 8) * ldc + c0) =
                        __floats2half2_rn(acc[mt][nt][2], acc[mt][nt][3]);
                }
        } else {
            float* Cb = (float*)Cout + (size_t)(mtile * CTA_M) * ldc
                      + (size_t)ntile * CTA_N;
#pragma unroll
            for (int mt = 0; mt < 4; mt++)
#pragma unroll
                for (int nt = 0; nt < 4; nt++) {
                    const int r0 = warp_m * 64 + mt * 16 + r_in;
                    const int c0 = warp_n * 32 + nt * 8 + c_in;
                    *(float2*)(Cb + (size_t)r0 * ldc + c0) =
                        make_float2(acc[mt][nt][0], acc[mt][nt][1]);
                    *(float2*)(Cb + (size_t)(r0 + 8) * ldc + c0) =
                        make_float2(acc[mt][nt][2], acc[mt][nt][3]);
                }
        }

        if (!PERSIST) break;
    }
}

// ============================================================================
// fused fp32 -> fp16 converter
// ============================================================================
__global__ void __launch_bounds__(256)
f2h_all(const float4* __restrict__ x,
        const float4* __restrict__ w0, const float4* __restrict__ w1,
        const float4* __restrict__ w2, const float4* __restrict__ w3,
        uint2* __restrict__ xdst, uint2* __restrict__ wdst)
{
    const int bx = blockIdx.x;
    const float4* src;
    uint2* dst;
    int i;
    if (bx < 16384) {
        i = bx * 256 + threadIdx.x;
        src = x; dst = xdst;
    } else {
        const int b = bx - 16384;
        const int mm = b >> 10;
        i = (b & 1023) * 256 + threadIdx.x;
        src = (mm == 0) ? w0 : (mm == 1) ? w1 : (mm == 2) ? w2 : w3;
        dst = wdst + (size_t)mm * 262144;
    }
    float4 v = src[i];
    __half2 h0 = __floats2half2_rn(v.x, v.y);
    __half2 h1 = __floats2half2_rn(v.z, v.w);
    uint2 o;
    o.x = *(uint32_t*)&h0;
    o.y = *(uint32_t*)&h1;
    dst[i] = o;
}

// ============================================================================
// Tensor-core per-token head attention (unchanged from R8).
// ============================================================================
#define TPAD 72
#define TOK_H (3 * 16 * TPAD)
#define ATTN_SMEM (8 * TOK_H * 2)

__global__ void __launch_bounds__(256)
attn_tc(const __half* __restrict__ Y, __half* __restrict__ O)
{
    extern __shared__ __align__(16) __half smh[];

    const int lane = threadIdx.x & 31;
    const int w    = threadIdx.x >> 5;
    const int m    = blockIdx.x * 8 + w;

    __half* tok = smh + w * TOK_H;
    const uint32_t tb = smem_u32(tok);

    const uint4* src = (const uint4*)(Y + (size_t)m * 3072);
#pragma unroll
    for (int it = 0; it < 12; it++) {
        const int f   = it * 32 + lane;
        const int sec = f >> 7;
        const int wi  = f & 127;
        const int row = wi >> 3;
        const int c8  = wi & 7;
        *(uint4*)(tok + sec * (16 * TPAD) + row * TPAD + c8 * 8) = src[f];
    }
    __syncwarp();

    const int rr = (lane & 7) + ((lane >> 3) & 1) * 8;
    const int cb = (lane >> 4) * 8;
    const uint32_t loff = (uint32_t)(rr * TPAD + cb) * 2;
    const uint32_t kbase = tb + 16 * TPAD * 2;
    const uint32_t vbase = tb + 32 * TPAD * 2;

    float s0[4] = {0.f, 0.f, 0.f, 0.f};
    float s1[4] = {0.f, 0.f, 0.f, 0.f};
#pragma unroll
    for (int kc = 0; kc < 4; kc++) {
        uint32_t a[4], kb[4];
        ldsm4(a[0], a[1], a[2], a[3], tb + loff + kc * 32);
        ldsm4(kb[0], kb[1], kb[2], kb[3], kbase + loff + kc * 32);
        uint32_t b0[2] = { kb[0], kb[2] };
        uint32_t b1[2] = { kb[1], kb[3] };
        mma_f16(s0, a, b0);
        mma_f16(s1, a, b1);
    }

#pragma unroll
    for (int i = 0; i < 4; i++) { s0[i] *= 0.125f; s1[i] *= 0.125f; }

    float mA = fmaxf(fmaxf(s0[0], s0[1]), fmaxf(s1[0], s1[1]));
    float mB = fmaxf(fmaxf(s0[2], s0[3]), fmaxf(s1[2], s1[3]));
    mA = fmaxf(mA, __shfl_xor_sync(0xffffffff, mA, 1));
    mA = fmaxf(mA, __shfl_xor_sync(0xffffffff, mA, 2));
    mB = fmaxf(mB, __shfl_xor_sync(0xffffffff, mB, 1));
    mB = fmaxf(mB, __shfl_xor_sync(0xffffffff, mB, 2));

    float eA0 = __expf(s0[0] - mA), eA1 = __expf(s0[1] - mA);
    float eA2 = __expf(s1[0] - mA), eA3 = __expf(s1[1] - mA);
    float eB0 = __expf(s0[2] - mB), eB1 = __expf(s0[3] - mB);
    float eB2 = __expf(s1[2] - mB), eB3 = __expf(s1[3] - mB);

    float sA = eA0 + eA1 + eA2 + eA3;
    float sB = eB0 + eB1 + eB2 + eB3;
    sA += __shfl_xor_sync(0xffffffff, sA, 1);
    sA += __shfl_xor_sync(0xffffffff, sA, 2);
    sB += __shfl_xor_sync(0xffffffff, sB, 1);
    sB += __shfl_xor_sync(0xffffffff, sB, 2);
    const float iA = 1.f / sA, iB = 1.f / sB;

    uint32_t pa[4];
    __half2 h;
    h = __floats2half2_rn(eA0 * iA, eA1 * iA); pa[0] = *(uint32_t*)&h;
    h = __floats2half2_rn(eB0 * iB, eB1 * iB); pa[1] = *(uint32_t*)&h;
    h = __floats2half2_rn(eA2 * iA, eA3 * iA); pa[2] = *(uint32_t*)&h;
    h = __floats2half2_rn(eB2 * iB, eB3 * iB); pa[3] = *(uint32_t*)&h;

    float oc[8][4];
#pragma unroll
    for (int i = 0; i < 8; i++)
#pragma unroll
        for (int j = 0; j < 4; j++) oc[i][j] = 0.f;

#pragma unroll
    for (int dc = 0; dc < 4; dc++) {
        uint32_t vb[4];
        ldsm4t(vb[0], vb[1], vb[2], vb[3], vbase + loff + dc * 32);
        uint32_t bt0[2] = { vb[0], vb[1] };
        uint32_t bt1[2] = { vb[2], vb[3] };
        mma_f16(oc[2 * dc], pa, bt0);
        mma_f16(oc[2 * dc + 1], pa, bt1);
    }

    __half* dst = O + (size_t)m * 1024;
    const int r = lane >> 2;
    const int q2 = 2 * (lane & 3);
#pragma unroll
    for (int i = 0; i < 8; i++) {
        const int col = (i >> 1) * 16 + (i & 1) * 8 + q2;
        *(__half2*)(dst + r * 64 + col) =
            __floats2half2_rn(oc[i][0], oc[i][1]);
        *(__half2*)(dst + (r + 8) * 64 + col) =
            __floats2half2_rn(oc[i][2], oc[i][3]);
    }
}

// ============================================================================
extern "C" void kernel_launch(void* const* d_in, const int* in_sizes, int n_in,
                              void* d_out, int out_size)
{
    (void)in_sizes; (void)n_in; (void)out_size;
    const float* x   = (const float*)d_in[0];
    const float* Wq  = (const float*)d_in[1];
    const float* Wk  = (const float*)d_in[2];
    const float* Wv  = (const float*)d_in[3];
    const float* Wfc = (const float*)d_in[4];
    float* out = (float*)d_out;

    __half *Yh, *Oh, *Xh, *Wh;
    cudaGetSymbolAddress((void**)&Yh, g_Yh);
    cudaGetSymbolAddress((void**)&Oh, g_Oh);
    cudaGetSymbolAddress((void**)&Xh, g_Xh);
    cudaGetSymbolAddress((void**)&Wh, g_Wh);

    cudaFuncSetAttribute((const void*)gemm_f16_nt<true, true>,
                         cudaFuncAttributeMaxDynamicSharedMemorySize, SMEM_TOTAL);
    cudaFuncSetAttribute((const void*)gemm_f16_nt<false, false>,
                         cudaFuncAttributeMaxDynamicSharedMemorySize, SMEM_TOTAL);
    cudaFuncSetAttribute(attn_tc,
                         cudaFuncAttributeMaxDynamicSharedMemorySize, ATTN_SMEM);

    // fused fp16 conversion
    f2h_all<<<20480, 256>>>((const float4*)x,
                            (const float4*)Wq, (const float4*)Wk,
                            (const float4*)Wv, (const float4*)Wfc,
                            (uint2*)Xh, (uint2*)Wh);

    // GEMM1: Yh = Xh @ [Wq;Wk;Wv]^T  (persistent: 296 CTAs over 3072 tiles)
    gemm_f16_nt<true, true><<<PERSIST_CTAS, 256, SMEM_TOTAL>>>(
        Xh, Wh, Yh, 3072, 1024, 24, 24 * 128);
    // tensor-core attention (8 tokens per block)
    attn_tc<<<2048, 256, ATTN_SMEM>>>(Yh, Oh);
    // GEMM2: out = Oh @ Wfc^T        (non-persistent: 8 x 128 grid)
    gemm_f16_nt<false, false><<<dim3(8, 128), 256, SMEM_TOTAL>>>(
        Oh, Wh + 3145728, out, 1024, 1024, 8, 8 * 128);
}

// round 14
// speedup vs baseline: 1.0185x; 1.0137x over previous
#include <cuda_runtime.h>
#include <cuda_fp16.h>
#include <cstdint>
#include <cstddef>

// ============================================================================
// MultiHeadAttention on GB300 — FP16 mma.sync everywhere.
//   conv : x, W -> fp16 (single fused launch, 32B/thread)
//   GEMM1: Yh[16384,3072] = Xh @ Wqkv^T  (CTA 128x128, warp 64x32, 2 CTA/SM,
//          4-stage cp.async + register fragment double-buffering)
//   attn : per-token 16x16 head attention on tensor cores
//   GEMM2: out(fp32) = Oh @ Wfc^T  (same kernel)
// ============================================================================

#define NSTG 4
#define STAGE_B 16384          // A 8KB + B 8KB
#define CTA_M 128
#define CTA_N 128
#define SMEM_TOTAL (NSTG * STAGE_B)   // 65536

__device__ __half g_Yh[50331648];   // 16384 x 3072
__device__ __half g_Oh[16777216];   // 16384 x 1024
__device__ __half g_Xh[16777216];   // x in fp16
__device__ __half g_Wh[4194304];    // Wq|Wk|Wv|Wfc in fp16

// ---------------------------------------------------------------- helpers
__device__ __forceinline__ uint32_t smem_u32(const void* p) {
    uint32_t a;
    asm("{ .reg .u64 t; cvta.to.shared.u64 t, %1; cvt.u32.u64 %0, t; }"
        : "=r"(a) : "l"(p));
    return a;
}
__device__ __forceinline__ void cp16(uint32_t saddr, const void* gptr) {
    asm volatile("cp.async.cg.shared.global [%0], [%1], 16;\n" :: "r"(saddr), "l"(gptr));
}
__device__ __forceinline__ void cp_commit() { asm volatile("cp.async.commit_group;\n"); }
template <int N>
__device__ __forceinline__ void cp_wait() {
    asm volatile("cp.async.wait_group %0;\n" :: "n"(N));
}
__device__ __forceinline__ void ldsm4(uint32_t& r0, uint32_t& r1, uint32_t& r2,
                                      uint32_t& r3, uint32_t addr) {
    asm volatile("ldmatrix.sync.aligned.m8n8.x4.shared.b16 {%0,%1,%2,%3}, [%4];"
                 : "=r"(r0), "=r"(r1), "=r"(r2), "=r"(r3) : "r"(addr));
}
__device__ __forceinline__ void ldsm4t(uint32_t& r0, uint32_t& r1, uint32_t& r2,
                                       uint32_t& r3, uint32_t addr) {
    asm volatile("ldmatrix.sync.aligned.m8n8.x4.trans.shared.b16 {%0,%1,%2,%3}, [%4];"
                 : "=r"(r0), "=r"(r1), "=r"(r2), "=r"(r3) : "r"(addr));
}
__device__ __forceinline__ void mma_f16(float c[4], const uint32_t a[4], const uint32_t b[2]) {
    asm volatile(
        "mma.sync.aligned.m16n8k16.row.col.f32.f16.f16.f32 "
        "{%0,%1,%2,%3}, {%4,%5,%6,%7}, {%8,%9}, {%0,%1,%2,%3};\n"
        : "+f"(c[0]), "+f"(c[1]), "+f"(c[2]), "+f"(c[3])
        : "r"(a[0]), "r"(a[1]), "r"(a[2]), "r"(a[3]), "r"(b[0]), "r"(b[1]));
}

// ============================================================================
// FP16 NT GEMM: C[128x128 tile] = A[M,K] @ B[N,K]^T
// 8 warps, warp tile 64x32, 2 CTA/SM. K multiple of 128.
// Register fragment double-buffering across the k-tile barrier.
// ============================================================================
template <bool OUT_HALF>
__global__ void __launch_bounds__(256, 2)
gemm_f16_nt(const __half* __restrict__ A, const __half* __restrict__ B,
            void* __restrict__ Cout, int ldc, int K)
{
    extern __shared__ __align__(128) char smem[];
    const uint32_t sb = smem_u32(smem);

    const int tid  = threadIdx.x;
    const int lane = tid & 31;
    const int wid  = tid >> 5;
    const int warp_m = wid & 1;     // 64 rows
    const int warp_n = wid >> 1;    // 32 cols

    const int mtile = blockIdx.y, ntile = blockIdx.x;
    const __half* Ab = A + (size_t)(mtile * CTA_M) * K;
    const __half* Bb = B + (size_t)(ntile * CTA_N) * K;

    // -------- loader: 4x cp16 per thread per k-tile
    const __half* gsrc[4];
    uint32_t soff[4];
#pragma unroll
    for (int i = 0; i < 4; i++) {
        const int id = tid + i * 256;       // 0..1023
        const int op = id >> 9;             // 0=A 1=B
        const int rr = (id >> 2) & 127;
        const int g  = id & 3;
        gsrc[i] = (op ? Bb : Ab) + (size_t)rr * K + g * 8;
        soff[i] = (uint32_t)(op * 8192 + rr * 64 + ((g ^ ((rr >> 1) & 3)) << 4));
    }

    // -------- ldmatrix fragment base addresses (stage 0, ks=0)
    const int ch = lane >> 4;
    uint32_t a_addr[4], b_addr[2];
#pragma unroll
    for (int mt = 0; mt < 4; mt++) {
        const int r = warp_m * 64 + mt * 16 + (lane & 15);
        a_addr[mt] = sb + r * 64 + ((ch ^ ((r >> 1) & 3)) << 4);
    }
#pragma unroll
    for (int p = 0; p < 2; p++) {
        const int r = warp_n * 32 + p * 16 + (lane & 15);
        b_addr[p] = sb + 8192 + r * 64 + ((ch ^ ((r >> 1) & 3)) << 4);
    }

    float acc[4][4][4];
#pragma unroll
    for (int mt = 0; mt < 4; mt++)
#pragma unroll
        for (int nt = 0; nt < 4; nt++)
#pragma unroll
            for (int i = 0; i < 4; i++) acc[mt][nt][i] = 0.f;

    // fragment slots (double-buffered)
    uint32_t aS[2][4][4], bS[2][4][2];

    auto ld_slot = [&](int s, uint32_t so, uint32_t kx) {
#pragma unroll
        for (int mt = 0; mt < 4; mt++)
            ldsm4(aS[s][mt][0], aS[s][mt][1], aS[s][mt][2], aS[s][mt][3],
                  (a_addr[mt] + so) ^ kx);
#pragma unroll
        for (int p = 0; p < 2; p++) {
            uint32_t t0, t1, t2, t3;
            ldsm4(t0, t1, t2, t3, (b_addr[p] + so) ^ kx);
            bS[s][2 * p][0] = t0; bS[s][2 * p][1] = t2;
            bS[s][2 * p + 1][0] = t1; bS[s][2 * p + 1][1] = t3;
        }
    };
    auto do_mma = [&](int s) {
#pragma unroll
        for (int mt = 0; mt < 4; mt++)
#pragma unroll
            for (int nt = 0; nt < 4; nt++)
                mma_f16(acc[mt][nt], aS[s][mt], bS[s][nt]);
    };

    const int NKT = K >> 5;   // multiple of 4

    // prefill stages 0..2 with tiles 0..2
#pragma unroll
    for (int s = 0; s < NSTG - 1; s++) {
#pragma unroll
        for (int i = 0; i < 4; i++) cp16(sb + s * STAGE_B + soff[i], gsrc[i] + s * 32);
        cp_commit();
    }

    // preload fragments for (tile 0, ks 0) into slot 0
    cp_wait<2>();
    __syncthreads();
    ld_slot(0, 0, 0);

    for (int kt0 = 0; kt0 < NKT; kt0 += 4) {
#pragma unroll
        for (int u = 0; u < 4; u++) {
            // invariants: slot0 holds (kt0+u, ks0); tile kt0+u in stage u
            cp_wait<1>();            // tiles kt, kt+1 resident
            __syncthreads();         // stage (u+3)&3 fully consumed by all warps

            const int nk = kt0 + u + 3;
            const uint32_t sw = (uint32_t)((u + 3) & 3) * STAGE_B;
            if (nk < NKT) {
#pragma unroll
                for (int i = 0; i < 4; i++) cp16(sb + sw + soff[i], gsrc[i] + nk * 32);
            }
            cp_commit();

            const uint32_t so  = (uint32_t)u * STAGE_B;             // this tile
            const uint32_t son = (uint32_t)((u + 1) & 3) * STAGE_B; // next tile

            ld_slot(1, so, 32);      // (kt, ks1)
            do_mma(0);               // (kt, ks0) — operands ready at entry
            ld_slot(0, son, 0);      // (kt+1, ks0); stale on last iter, unused
            do_mma(1);               // (kt, ks1)
        }
    }

    // -------- epilogue (registers only)
    const int r_in = lane >> 2;
    const int c_in = 2 * (lane & 3);
    if (OUT_HALF) {
        __half* Cb = (__half*)Cout + (size_t)(mtile * CTA_M) * ldc
                   + (size_t)ntile * CTA_N;
#pragma unroll
        for (int mt = 0; mt < 4; mt++)
#pragma unroll
            for (int nt = 0; nt < 4; nt++) {
                const int r0 = warp_m * 64 + mt * 16 + r_in;
                const int c0 = warp_n * 32 + nt * 8 + c_in;
                *(__half2*)(Cb + (size_t)r0 * ldc + c0) =
                    __floats2half2_rn(acc[mt][nt][0], acc[mt][nt][1]);
                *(__half2*)(Cb + (size_t)(r0 + 8) * ldc + c0) =
                    __floats2half2_rn(acc[mt][nt][2], acc[mt][nt][3]);
            }
    } else {
        float* Cb = (float*)Cout + (size_t)(mtile * CTA_M) * ldc
                  + (size_t)ntile * CTA_N;
#pragma unroll
        for (int mt = 0; mt < 4; mt++)
#pragma unroll
            for (int nt = 0; nt < 4; nt++) {
                const int r0 = warp_m * 64 + mt * 16 + r_in;
                const int c0 = warp_n * 32 + nt * 8 + c_in;
                *(float2*)(Cb + (size_t)r0 * ldc + c0) =
                    make_float2(acc[mt][nt][0], acc[mt][nt][1]);
                *(float2*)(Cb + (size_t)(r0 + 8) * ldc + c0) =
                    make_float2(acc[mt][nt][2], acc[mt][nt][3]);
            }
    }
}

// ============================================================================
// fused fp32 -> fp16 converter: 2x float4 in, 1x uint4 out per thread.
// blocks [0,8192) = x (8 floats/thread), [8192,10240) = weights
// ============================================================================
__global__ void __launch_bounds__(256)
f2h_all(const float4* __restrict__ x,
        const float4* __restrict__ w0, const float4* __restrict__ w1,
        const float4* __restrict__ w2, const float4* __restrict__ w3,
        uint4* __restrict__ xdst, uint4* __restrict__ wdst)
{
    const int bx = blockIdx.x;
    const float4* src;
    uint4* dst;
    int i;    // uint4 index (8 halves)
    if (bx < 8192) {
        i = bx * 256 + threadIdx.x;          // 0..2097151
        src = x; dst = xdst;
    } else {
        const int b = bx - 8192;             // 0..2047
        const int mm = b >> 9;               // matrix
        i = (b & 511) * 256 + threadIdx.x;   // 0..131071
        src = (mm == 0) ? w0 : (mm == 1) ? w1 : (mm == 2) ? w2 : w3;
        dst = wdst + (size_t)mm * 131072;
    }
    float4 v0 = src[2 * i];
    float4 v1 = src[2 * i + 1];
    __half2 h0 = __floats2half2_rn(v0.x, v0.y);
    __half2 h1 = __floats2half2_rn(v0.z, v0.w);
    __half2 h2 = __floats2half2_rn(v1.x, v1.y);
    __half2 h3 = __floats2half2_rn(v1.z, v1.w);
    uint4 o;
    o.x = *(uint32_t*)&h0;
    o.y = *(uint32_t*)&h1;
    o.z = *(uint32_t*)&h2;
    o.w = *(uint32_t*)&h3;
    dst[i] = o;
}

// ============================================================================
// Tensor-core per-token head attention (unchanged from R8).
// ============================================================================
#define TPAD 72
#define TOK_H (3 * 16 * TPAD)
#define ATTN_SMEM (8 * TOK_H * 2)

__global__ void __launch_bounds__(256)
attn_tc(const __half* __restrict__ Y, __half* __restrict__ O)
{
    extern __shared__ __align__(16) __half smh[];

    const int lane = threadIdx.x & 31;
    const int w    = threadIdx.x >> 5;
    const int m    = blockIdx.x * 8 + w;

    __half* tok = smh + w * TOK_H;
    const uint32_t tb = smem_u32(tok);

    const uint4* src = (const uint4*)(Y + (size_t)m * 3072);
#pragma unroll
    for (int it = 0; it < 12; it++) {
        const int f   = it * 32 + lane;
        const int sec = f >> 7;
        const int wi  = f & 127;
        const int row = wi >> 3;
        const int c8  = wi & 7;
        *(uint4*)(tok + sec * (16 * TPAD) + row * TPAD + c8 * 8) = src[f];
    }
    __syncwarp();

    const int rr = (lane & 7) + ((lane >> 3) & 1) * 8;
    const int cb = (lane >> 4) * 8;
    const uint32_t loff = (uint32_t)(rr * TPAD + cb) * 2;
    const uint32_t kbase = tb + 16 * TPAD * 2;
    const uint32_t vbase = tb + 32 * TPAD * 2;

    float s0[4] = {0.f, 0.f, 0.f, 0.f};
    float s1[4] = {0.f, 0.f, 0.f, 0.f};
#pragma unroll
    for (int kc = 0; kc < 4; kc++) {
        uint32_t a[4], kb[4];
        ldsm4(a[0], a[1], a[2], a[3], tb + loff + kc * 32);
        ldsm4(kb[0], kb[1], kb[2], kb[3], kbase + loff + kc * 32);
        uint32_t b0[2] = { kb[0], kb[2] };
        uint32_t b1[2] = { kb[1], kb[3] };
        mma_f16(s0, a, b0);
        mma_f16(s1, a, b1);
    }

#pragma unroll
    for (int i = 0; i < 4; i++) { s0[i] *= 0.125f; s1[i] *= 0.125f; }

    float mA = fmaxf(fmaxf(s0[0], s0[1]), fmaxf(s1[0], s1[1]));
    float mB = fmaxf(fmaxf(s0[2], s0[3]), fmaxf(s1[2], s1[3]));
    mA = fmaxf(mA, __shfl_xor_sync(0xffffffff, mA, 1));
    mA = fmaxf(mA, __shfl_xor_sync(0xffffffff, mA, 2));
    mB = fmaxf(mB, __shfl_xor_sync(0xffffffff, mB, 1));
    mB = fmaxf(mB, __shfl_xor_sync(0xffffffff, mB, 2));

    float eA0 = __expf(s0[0] - mA), eA1 = __expf(s0[1] - mA);
    float eA2 = __expf(s1[0] - mA), eA3 = __expf(s1[1] - mA);
    float eB0 = __expf(s0[2] - mB), eB1 = __expf(s0[3] - mB);
    float eB2 = __expf(s1[2] - mB), eB3 = __expf(s1[3] - mB);

    float sA = eA0 + eA1 + eA2 + eA3;
    float sB = eB0 + eB1 + eB2 + eB3;
    sA += __shfl_xor_sync(0xffffffff, sA, 1);
    sA += __shfl_xor_sync(0xffffffff, sA, 2);
    sB += __shfl_xor_sync(0xffffffff, sB, 1);
    sB += __shfl_xor_sync(0xffffffff, sB, 2);
    const float iA = 1.f / sA, iB = 1.f / sB;

    uint32_t pa[4];
    __half2 h;
    h = __floats2half2_rn(eA0 * iA, eA1 * iA); pa[0] = *(uint32_t*)&h;
    h = __floats2half2_rn(eB0 * iB, eB1 * iB); pa[1] = *(uint32_t*)&h;
    h = __floats2half2_rn(eA2 * iA, eA3 * iA); pa[2] = *(uint32_t*)&h;
    h = __floats2half2_rn(eB2 * iB, eB3 * iB); pa[3] = *(uint32_t*)&h;

    float oc[8][4];
#pragma unroll
    for (int i = 0; i < 8; i++)
#pragma unroll
        for (int j = 0; j < 4; j++) oc[i][j] = 0.f;

#pragma unroll
    for (int dc = 0; dc < 4; dc++) {
        uint32_t vb[4];
        ldsm4t(vb[0], vb[1], vb[2], vb[3], vbase + loff + dc * 32);
        uint32_t bt0[2] = { vb[0], vb[1] };
        uint32_t bt1[2] = { vb[2], vb[3] };
        mma_f16(oc[2 * dc], pa, bt0);
        mma_f16(oc[2 * dc + 1], pa, bt1);
    }

    __half* dst = O + (size_t)m * 1024;
    const int r = lane >> 2;
    const int q2 = 2 * (lane & 3);
#pragma unroll
    for (int i = 0; i < 8; i++) {
        const int col = (i >> 1) * 16 + (i & 1) * 8 + q2;
        *(__half2*)(dst + r * 64 + col) =
            __floats2half2_rn(oc[i][0], oc[i][1]);
        *(__half2*)(dst + (r + 8) * 64 + col) =
            __floats2half2_rn(oc[i][2], oc[i][3]);
    }
}

// ============================================================================
extern "C" void kernel_launch(void* const* d_in, const int* in_sizes, int n_in,
                              void* d_out, int out_size)
{
    (void)in_sizes; (void)n_in; (void)out_size;
    const float* x   = (const float*)d_in[0];
    const float* Wq  = (const float*)d_in[1];
    const float* Wk  = (const float*)d_in[2];
    const float* Wv  = (const float*)d_in[3];
    const float* Wfc = (const float*)d_in[4];
    float* out = (float*)d_out;

    __half *Yh, *Oh, *Xh, *Wh;
    cudaGetSymbolAddress((void**)&Yh, g_Yh);
    cudaGetSymbolAddress((void**)&Oh, g_Oh);
    cudaGetSymbolAddress((void**)&Xh, g_Xh);
    cudaGetSymbolAddress((void**)&Wh, g_Wh);

    cudaFuncSetAttribute(gemm_f16_nt<true>,
                         cudaFuncAttributeMaxDynamicSharedMemorySize, SMEM_TOTAL);
    cudaFuncSetAttribute(gemm_f16_nt<false>,
                         cudaFuncAttributeMaxDynamicSharedMemorySize, SMEM_TOTAL);
    cudaFuncSetAttribute(attn_tc,
                         cudaFuncAttributeMaxDynamicSharedMemorySize, ATTN_SMEM);

    // fused fp16 conversion (32B/thread)
    f2h_all<<<10240, 256>>>((const float4*)x,
                            (const float4*)Wq, (const float4*)Wk,
                            (const float4*)Wv, (const float4*)Wfc,
                            (uint4*)Xh, (uint4*)Wh);

    // GEMM1: Yh = Xh @ [Wq;Wk;Wv]^T   (tiles: 24 x 128)
    gemm_f16_nt<true><<<dim3(24, 128), 256, SMEM_TOTAL>>>(Xh, Wh, Yh, 3072, 1024);
    // tensor-core attention (8 tokens per block)
    attn_tc<<<2048, 256, ATTN_SMEM>>>(Yh, Oh);
    // GEMM2: out = Oh @ Wfc^T         (tiles: 8 x 128)
    gemm_f16_nt<false><<<dim3(8, 128), 256, SMEM_TOTAL>>>(Oh, Wh + 3145728, out, 1024, 1024);
}